// round 17
// baseline (speedup 1.0000x reference)
#include <cuda_runtime.h>
#include <math.h>

#define VOCAB 50257
#define BATCH 512
#define SEQ   512
#define EMBED 256
#define EV4   (EMBED / 4)   // 64 float4 per embedding row
#define OUTC  5
#define PROJ_STRIDE 8       // padded floats per vocab entry (32 B aligned)
#define GRID  592           // 148 SMs x 4 CTAs co-resident (regs forced <=64)
#define NTILES ((VOCAB + 3) / 4)   // 12565 four-row tiles
#define WPAD  41            // 8*5 + 1 float4: bank-conflict-free W layout

// Device scratch (mallocs forbidden). Counters zero at load and reset
// in-kernel every call -> graph-replay safe.
__device__ float        g_proj[(size_t)VOCAB * PROJ_STRIDE];  // ~1.6 MB
__device__ float        g_loss[BATCH];
__device__ unsigned int g_arrive;   // grid-barrier arrivals
__device__ unsigned int g_done;     // grid-barrier departures (guards reset)
__device__ unsigned int g_count;    // CTA completions for final mean

__device__ __forceinline__ float dot4(const float4& a, const float4& b) {
    return a.x * b.x + a.y * b.y + a.z * b.z + a.w * b.w;
}

__global__ __launch_bounds__(256, 4)
void fused_kernel(const int*   __restrict__ input_x,
                  const int*   __restrict__ lengths,
                  const int*   __restrict__ input_y,
                  const float* __restrict__ emb,
                  const float* __restrict__ W,
                  const float* __restrict__ bias,
                  float*       __restrict__ out)
{
    __shared__ float4 s_W[8 * WPAD];    // padded: [seg][k][o] -> seg*41+k*5+o
    __shared__ float  s_red[8][OUTC];
    __shared__ float  s_sum[256];
    __shared__ int    s_last;

    const int tid  = threadIdx.x;
    const int lane = tid & 31;
    const int wid  = tid >> 5;

    // Stage W: s_W[seg*41 + k*5 + o] = W[o][seg*8+k]  (320 entries, looped)
    {
        const float4* __restrict__ Wv = (const float4*)W;
        for (int i = tid; i < OUTC * 64; i += 256) {
            const int o  = i >> 6;
            const int c4 = i & 63;
            const int sg = c4 >> 3;
            const int k  = c4 & 7;
            s_W[sg * WPAD + k * 5 + o] = Wv[o * 64 + c4];
        }
    }
    __syncthreads();

    // ====== Phase 1: proj = emb . W^T, 4 rows per warp-tile ================
    // lane -> (rloc = lane>>3, seg = lane&7). Lane owns the CONTIGUOUS 128 B
    // slice [seg*128, seg*128+128) of its row -> 8 front-batched LDG.128
    // (plain caching; R15's evict_last hint poisoned L2 and is removed).
    {
        const int nwarps = GRID * 8;                 // 4736
        const int gw     = (blockIdx.x << 3) + wid;
        const int rloc   = lane >> 3;                // 0..3
        const int seg    = lane & 7;                 // 0..7

        for (int tile = gw; tile < NTILES; tile += nwarps) {  // warp-uniform
            const int  row   = tile * 4 + rloc;
            const bool valid = row < VOCAB;
            const int  rowc  = valid ? row : (VOCAB - 1);     // clamp (shfl-safe)
            const float4* base =
                (const float4*)(emb + (long)rowc * EMBED + seg * 32);

            // Front-batch the lane's 8 x 128-bit loads (MLP = 8)
            float4 e[8];
            #pragma unroll
            for (int i = 0; i < 8; i++) e[i] = base[i];

            float acc[OUTC];
            #pragma unroll
            for (int o = 0; o < OUTC; o++) acc[o] = 0.f;

            #pragma unroll
            for (int k = 0; k < 8; k++) {
                const float4* wp = &s_W[seg * WPAD + k * 5];
                acc[0] += dot4(e[k], wp[0]);
                acc[1] += dot4(e[k], wp[1]);
                acc[2] += dot4(e[k], wp[2]);
                acc[3] += dot4(e[k], wp[3]);
                acc[4] += dot4(e[k], wp[4]);
            }

            // Reduce across the 8-lane segment group (all lanes converged)
            #pragma unroll
            for (int o = 0; o < OUTC; o++) {
                acc[o] += __shfl_xor_sync(0xffffffffu, acc[o], 4);
                acc[o] += __shfl_xor_sync(0xffffffffu, acc[o], 2);
                acc[o] += __shfl_xor_sync(0xffffffffu, acc[o], 1);
            }

            if (valid && seg == 0) {
                *(float4*)&g_proj[(long)row * PROJ_STRIDE] =
                    make_float4(acc[0], acc[1], acc[2], acc[3]);
                g_proj[(long)row * PROJ_STRIDE + 4] = acc[4];
            }
        }
    }

    // ====== Grid-wide barrier (592 CTAs co-resident at occ 4) ==============
    __threadfence();            // release g_proj
    __syncthreads();
    if (tid == 0) {
        atomicAdd(&g_arrive, 1u);
        while (*(volatile unsigned int*)&g_arrive < GRID) __nanosleep(64);
        if (atomicAdd(&g_done, 1u) == GRID - 1) {   // all passed the spin
            g_arrive = 0;
            g_done   = 0;
        }
    }
    __syncthreads();
    __threadfence();            // acquire g_proj

    // ====== Phase 2: per-sample loss (CTAs 0..511) =========================
    if (blockIdx.x < BATCH) {
        const int b   = blockIdx.x;
        const int len = lengths[b];
        const int* xrow = input_x + b * SEQ;

        float acc[OUTC];
        #pragma unroll
        for (int o = 0; o < OUTC; o++) acc[o] = 0.f;

        if (tid < len) {
            const int t = xrow[tid];
            float4 p = *(const float4*)&g_proj[(long)t * PROJ_STRIDE];
            float  q = g_proj[(long)t * PROJ_STRIDE + 4];
            acc[0] += p.x; acc[1] += p.y; acc[2] += p.z; acc[3] += p.w; acc[4] += q;
        }
        if (tid + 256 < len) {
            const int t = xrow[tid + 256];
            float4 p = *(const float4*)&g_proj[(long)t * PROJ_STRIDE];
            float  q = g_proj[(long)t * PROJ_STRIDE + 4];
            acc[0] += p.x; acc[1] += p.y; acc[2] += p.z; acc[3] += p.w; acc[4] += q;
        }

        #pragma unroll
        for (int o = 0; o < OUTC; o++) {
            #pragma unroll
            for (int off = 16; off > 0; off >>= 1)
                acc[o] += __shfl_down_sync(0xffffffffu, acc[o], off);
        }
        if (lane == 0) {
            #pragma unroll
            for (int o = 0; o < OUTC; o++) s_red[wid][o] = acc[o];
        }
        __syncthreads();

        if (tid == 0) {
            float tot[OUTC];
            #pragma unroll
            for (int o = 0; o < OUTC; o++) {
                tot[o] = ((s_red[0][o] + s_red[1][o]) + (s_red[2][o] + s_red[3][o]))
                       + ((s_red[4][o] + s_red[5][o]) + (s_red[6][o] + s_red[7][o]));
            }
            const float inv_len = 1.0f / (float)len;
            float logits[OUTC];
            float m = -INFINITY;
            #pragma unroll
            for (int o = 0; o < OUTC; o++) {
                logits[o] = tot[o] * inv_len + bias[o];
                m = fmaxf(m, logits[o]);
            }
            float se = 0.f;
            #pragma unroll
            for (int o = 0; o < OUTC; o++) se += __expf(logits[o] - m);
            const float lse = m + __logf(se);
            const int y = input_y[b];
            g_loss[b] = lse - logits[y];
        }
    }

    // ====== Final mean via last-CTA pattern ================================
    __syncthreads();
    if (tid == 0) {
        __threadfence();
        s_last = (atomicAdd(&g_count, 1u) == GRID - 1) ? 1 : 0;
    }
    __syncthreads();

    if (s_last) {
        __threadfence();
        s_sum[tid] = g_loss[tid] + g_loss[tid + 256];
        __syncthreads();
        #pragma unroll
        for (int off = 128; off > 0; off >>= 1) {
            if (tid < off) s_sum[tid] += s_sum[tid + off];
            __syncthreads();
        }
        if (tid == 0) {
            out[0] = s_sum[0] * (1.0f / (float)BATCH);
            g_count = 0;   // reset for next replay
        }
    }
}

extern "C" void kernel_launch(void* const* d_in, const int* in_sizes, int n_in,
                              void* d_out, int out_size)
{
    const int*   input_x = (const int*)d_in[0];
    const int*   lengths = (const int*)d_in[1];
    const int*   input_y = (const int*)d_in[2];
    const float* emb     = (const float*)d_in[3];
    const float* W       = (const float*)d_in[4];
    const float* bias    = (const float*)d_in[5];
    float* out = (float*)d_out;

    fused_kernel<<<GRID, 256>>>(input_x, lengths, input_y, emb, W, bias, out);
}